// round 9
// baseline (speedup 1.0000x reference)
#include <cuda_runtime.h>

// VQC simulator: NQ=10, NL=4, B=2048, C=4.
// One warp per batch element; 1024 complex amps in registers, PACKED f32x2:
//   qubit q <-> flat bit (9-q); lane = bits[9:5] (q0..4),
//   pack t = bits[4:1] (q5..8), half = bit0 (q9).
// All gate matrices are SU(2): M = [[a, b], [-conj(b), conj(a)]].
// Reg budget: launch_bounds(32,20) caps at 102 regs -> 20 warps/SM, one wave.

#define NQ 10
#define NL 4
#define BATCH 2048

typedef unsigned long long ull;

__device__ __forceinline__ ull mul2(ull a, ull b) {
    ull d; asm("mul.rn.f32x2 %0, %1, %2;" : "=l"(d) : "l"(a), "l"(b)); return d;
}
__device__ __forceinline__ ull fma2(ull a, ull b, ull c) {
    ull d; asm("fma.rn.f32x2 %0, %1, %2, %3;" : "=l"(d) : "l"(a), "l"(b), "l"(c)); return d;
}
__device__ __forceinline__ ull pk(float v) {
    ull d; asm("mov.b64 %0, {%1, %1};" : "=l"(d) : "f"(v)); return d;
}
__device__ __forceinline__ ull pack2(float x, float y) {
    ull d; asm("mov.b64 %0, {%1, %2};" : "=l"(d) : "f"(x), "f"(y)); return d;
}
__device__ __forceinline__ float2 unpack2(ull v) {
    float2 r; asm("mov.b64 {%0, %1}, %2;" : "=f"(r.x), "=f"(r.y) : "l"(v)); return r;
}

// SU(2) gate: (a, b) complex; M = [[a, b], [-conj(b), conj(a)]].
struct Gate { float ar, ai, br, bi; };

// Fused M = Rot * RX from Rot top row and RX half-angle xh.
__device__ __forceinline__ Gate fuse(float4 r, float xh) {
    float s, c;
    __sincosf(xh, &s, &c);
    Gate G;
    G.ar = r.x * c + r.w * s;
    G.ai = r.y * c - r.z * s;
    G.br = r.y * s + r.z * c;
    G.bi = r.w * c - r.x * s;
    return G;
}

// 1q gate on a lane bit (q0..4): packed arithmetic, shfl halves.
template <int LM>
__device__ __forceinline__ void gate_lane(ull (&R)[16], ull (&I)[16],
                                          const Gate& G, int lane) {
    const bool hi = (lane & LM) != 0;
    const float cai = hi ? -G.ai : G.ai;
    const float cbr = hi ? -G.br : G.br;
    const ull Par = pk(G.ar), Pai = pk(cai), Nai = pk(-cai);
    const ull Pbr = pk(cbr), Pbi = pk(G.bi), Nbi = pk(-G.bi);
#pragma unroll
    for (int t = 0; t < 16; t++) {
        float2 r = unpack2(R[t]), i = unpack2(I[t]);
        float prx = __shfl_xor_sync(0xffffffffu, r.x, LM);
        float pry = __shfl_xor_sync(0xffffffffu, r.y, LM);
        float pix = __shfl_xor_sync(0xffffffffu, i.x, LM);
        float piy = __shfl_xor_sync(0xffffffffu, i.y, LM);
        ull PR = pack2(prx, pry), PI = pack2(pix, piy);
        ull nr = fma2(Nbi, PI, fma2(Pbr, PR, fma2(Nai, I[t], mul2(Par, R[t]))));
        ull ni = fma2(Pbi, PR, fma2(Pbr, PI, fma2(Pai, R[t], mul2(Par, I[t]))));
        R[t] = nr; I[t] = ni;
    }
}

// 1q gate on pack bits (q5..8): 7 packed SU(2) constants.
template <int PM>
__device__ __forceinline__ void gate_local_p(ull (&R)[16], ull (&I)[16],
                                             const Gate& G) {
    const ull Par = pk(G.ar), Pai = pk(G.ai), Nai = pk(-G.ai);
    const ull Pbr = pk(G.br), Nbr = pk(-G.br), Pbi = pk(G.bi), Nbi = pk(-G.bi);
#pragma unroll
    for (int t = 0; t < 16; t++) {
        if ((t & PM) == 0) {
            const int u = t | PM;
            ull a0r = R[t], a0i = I[t], a1r = R[u], a1i = I[u];
            // out0 = a*x0 + b*x1 ; out1 = -conj(b)*x0 + conj(a)*x1
            R[t] = fma2(Nbi, a1i, fma2(Pbr, a1r, fma2(Nai, a0i, mul2(Par, a0r))));
            I[t] = fma2(Pbi, a1r, fma2(Pbr, a1i, fma2(Pai, a0r, mul2(Par, a0i))));
            R[u] = fma2(Pai, a1i, fma2(Par, a1r, fma2(Nbi, a0i, mul2(Nbr, a0r))));
            I[u] = fma2(Nai, a1r, fma2(Par, a1i, fma2(Pbi, a0r, mul2(Nbr, a0i))));
        }
    }
}

// 1q gate on qubit 9 (intra-pack halves): scalar SU(2).
__device__ __forceinline__ void gate_q9(ull (&R)[16], ull (&I)[16], const Gate& G) {
#pragma unroll
    for (int t = 0; t < 16; t++) {
        float2 r = unpack2(R[t]), i = unpack2(I[t]);
        float n0r = G.ar * r.x - G.ai * i.x + G.br * r.y - G.bi * i.y;
        float n0i = G.ar * i.x + G.ai * r.x + G.br * i.y + G.bi * r.y;
        float n1r = -G.br * r.x - G.bi * i.x + G.ar * r.y + G.ai * i.y;
        float n1i = -G.br * i.x + G.bi * r.x + G.ar * i.y - G.ai * r.y;
        R[t] = pack2(n0r, n1r);
        I[t] = pack2(n0i, n1i);
    }
}

// CNOT pack-swap: swap packs t <-> t|TP where (t & CP) && !(t & TP).
template <int CP, int TP>
__device__ __forceinline__ void cnot_pp(ull (&R)[16], ull (&I)[16]) {
#pragma unroll
    for (int t = 0; t < 16; t++) {
        if ((t & CP) != 0 && (t & TP) == 0) {
            const int u = t | TP;
            ull w;
            w = R[t]; R[t] = R[u]; R[u] = w;
            w = I[t]; I[t] = I[u]; I[u] = w;
        }
    }
}

// Fused lane-bit CNOT chain (0,1)(1,2)(2,3)(3,4): one lane permutation.
__device__ __forceinline__ void cnot_lane_chain(ull (&R)[16], ull (&I)[16],
                                                int lane) {
    int s = lane;
    if (s & 2)  s ^= 1;
    if (s & 4)  s ^= 2;
    if (s & 8)  s ^= 4;
    if (s & 16) s ^= 8;
#pragma unroll
    for (int t = 0; t < 16; t++) {
        float2 r = unpack2(R[t]), i = unpack2(I[t]);
        r.x = __shfl_sync(0xffffffffu, r.x, s);
        r.y = __shfl_sync(0xffffffffu, r.y, s);
        i.x = __shfl_sync(0xffffffffu, i.x, s);
        i.y = __shfl_sync(0xffffffffu, i.y, s);
        R[t] = pack2(r.x, r.y);
        I[t] = pack2(i.x, i.y);
    }
}

// CNOT(4,5): control lane bit0, target pack bit 3.
__device__ __forceinline__ void cnot_45(ull (&R)[16], ull (&I)[16], int lane) {
    if (lane & 1) {
#pragma unroll
        for (int t = 0; t < 8; t++) {
            const int u = t | 8;
            ull w;
            w = R[t]; R[t] = R[u]; R[u] = w;
            w = I[t]; I[t] = I[u]; I[u] = w;
        }
    }
}

// CNOT(8,9): control pack bit0, target intra-pack half.
__device__ __forceinline__ void cnot_89(ull (&R)[16], ull (&I)[16]) {
#pragma unroll
    for (int t = 1; t < 16; t += 2) {
        float2 r = unpack2(R[t]), i = unpack2(I[t]);
        R[t] = pack2(r.y, r.x);
        I[t] = pack2(i.y, i.x);
    }
}

// CNOT(9,0): control hi half, target lane bit 4: shfl hi halves.
__device__ __forceinline__ void cnot_90(ull (&R)[16], ull (&I)[16]) {
#pragma unroll
    for (int t = 0; t < 16; t++) {
        float2 r = unpack2(R[t]), i = unpack2(I[t]);
        r.y = __shfl_xor_sync(0xffffffffu, r.y, 16);
        i.y = __shfl_xor_sync(0xffffffffu, i.y, 16);
        R[t] = pack2(r.x, r.y);
        I[t] = pack2(i.x, i.y);
    }
}

__global__ __launch_bounds__(32, 20)
void vqc_kernel(const float* __restrict__ x, const float* __restrict__ weights,
                const float* __restrict__ bias, const float* __restrict__ osf,
                float* __restrict__ out) {
    // Rot top-row only (SU(2)): 4 floats per gate, float4-aligned.
    __shared__ float4 srot[NL * NQ];

    const int lane = threadIdx.x;
    const int b = blockIdx.x;

    // Precompute Rot matrices (batch-independent) once per CTA.
    for (int g = lane; g < NL * NQ; g += 32) {
        const float phi = weights[g * 3 + 0];
        const float th  = weights[g * 3 + 1];
        const float om  = weights[g * 3 + 2];
        float ssn, cc;  __sincosf(0.5f * th, &ssn, &cc);
        float sa, ca;   __sincosf(0.5f * (phi + om), &sa, &ca);
        float sb, cb;   __sincosf(0.5f * (phi - om), &sb, &cb);
        srot[g] = make_float4(ca * cc, -sa * cc, -cb * ssn, -sb * ssn);
    }
    __syncthreads();

    // Half-angles only (10 regs); sincos recomputed per gate to cut reg pressure.
    float xh[NQ];
#pragma unroll
    for (int q = 0; q < NQ; q++) xh[q] = 0.5f * x[b * NQ + q];

    // State |0...0>.
    ull R[16], I[16];
#pragma unroll
    for (int t = 0; t < 16; t++) { R[t] = 0ull; I[t] = 0ull; }
    if (lane == 0) R[0] = pack2(1.0f, 0.0f);

#pragma unroll 1
    for (int l = 0; l < NL; l++) {
        const float4* rl = &srot[l * NQ];

        // Fused (Rot*RX): q0..4 lane bits, q5..8 pack bits, q9 intra-pack.
        { Gate G = fuse(rl[0], xh[0]); gate_lane<16>(R, I, G, lane); }
        { Gate G = fuse(rl[1], xh[1]); gate_lane< 8>(R, I, G, lane); }
        { Gate G = fuse(rl[2], xh[2]); gate_lane< 4>(R, I, G, lane); }
        { Gate G = fuse(rl[3], xh[3]); gate_lane< 2>(R, I, G, lane); }
        { Gate G = fuse(rl[4], xh[4]); gate_lane< 1>(R, I, G, lane); }
        { Gate G = fuse(rl[5], xh[5]); gate_local_p<8>(R, I, G); }
        { Gate G = fuse(rl[6], xh[6]); gate_local_p<4>(R, I, G); }
        { Gate G = fuse(rl[7], xh[7]); gate_local_p<2>(R, I, G); }
        { Gate G = fuse(rl[8], xh[8]); gate_local_p<1>(R, I, G); }
        { Gate G = fuse(rl[9], xh[9]); gate_q9(R, I, G); }

        // Ring CNOTs (0,1)..(8,9),(9,0).
        cnot_lane_chain(R, I, lane);  // (0,1)(1,2)(2,3)(3,4)
        cnot_45(R, I, lane);          // (4,5)
        cnot_pp<8, 4>(R, I);          // (5,6)
        cnot_pp<4, 2>(R, I);          // (6,7)
        cnot_pp<2, 1>(R, I);          // (7,8)
        cnot_89(R, I);                // (8,9)
        cnot_90(R, I);                // (9,0)
    }

    // Probabilities + Z-expectations for qubits 0..3 (lane bits).
    float s = 0.0f;
#pragma unroll
    for (int t = 0; t < 16; t++) {
        float2 r = unpack2(R[t]), i = unpack2(I[t]);
        s = fmaf(r.x, r.x, s);
        s = fmaf(r.y, r.y, s);
        s = fmaf(i.x, i.x, s);
        s = fmaf(i.y, i.y, s);
    }

    float z0 = (lane & 16) ? -s : s;
    float z1 = (lane &  8) ? -s : s;
    float z2 = (lane &  4) ? -s : s;
    float z3 = (lane &  2) ? -s : s;
#pragma unroll
    for (int o = 16; o >= 1; o >>= 1) {
        z0 += __shfl_xor_sync(0xffffffffu, z0, o);
        z1 += __shfl_xor_sync(0xffffffffu, z1, o);
        z2 += __shfl_xor_sync(0xffffffffu, z2, o);
        z3 += __shfl_xor_sync(0xffffffffu, z3, o);
    }

    if (lane == 0) {
        float t0 = (z0 + bias[0]) * osf[0];
        float t1 = (z1 + bias[1]) * osf[1];
        float t2 = (z2 + bias[2]) * osf[2];
        float t3 = (z3 + bias[3]) * osf[3];
        float m = fmaxf(fmaxf(t0, t1), fmaxf(t2, t3));
        float e0 = __expf(t0 - m);
        float e1 = __expf(t1 - m);
        float e2 = __expf(t2 - m);
        float e3 = __expf(t3 - m);
        float inv = 1.0f / (e0 + e1 + e2 + e3);
        float4 o4 = make_float4(e0 * inv, e1 * inv, e2 * inv, e3 * inv);
        reinterpret_cast<float4*>(out)[b] = o4;
    }
}

extern "C" void kernel_launch(void* const* d_in, const int* in_sizes, int n_in,
                              void* d_out, int out_size) {
    const float* x       = (const float*)d_in[0];  // (2048, 10)
    const float* weights = (const float*)d_in[1];  // (4, 10, 3)
    const float* bias    = (const float*)d_in[2];  // (4,)
    const float* osf     = (const float*)d_in[3];  // (4,)
    float* out = (float*)d_out;                    // (2048, 4)

    vqc_kernel<<<BATCH, 32>>>(x, weights, bias, osf, out);
}